// round 1
// baseline (speedup 1.0000x reference)
#include <cuda_runtime.h>
#include <cuda_bf16.h>

// Problem constants
#define Bx 8
#define Lx 256
#define Dx 256
#define BLD (Bx*Lx*Dx)   // 524288
#define BLL (Bx*Lx*Lx)   // 524288

// Scratch (device globals — no allocation allowed)
__device__ float g_A[BLD];   // Q @ Wa^T
__device__ float g_Bm[BLD];  // Q @ Wb^T
__device__ float g_H[BLD];   // Q @ Wd^T
__device__ float g_W[BLL];   // softmax weights

// ---------------------------------------------------------------------------
// Kernel 1: projections. C[m,n] = sum_k X[m,k] * W[n,k]  (NT GEMM)
// M = B*L = 2048, N = 256, K = 256. blockIdx.z picks {Wa,Wb,Wd}.
// BM=64, BN=64, BK=16, 256 threads, 4x4 per thread.
// ---------------------------------------------------------------------------
__global__ __launch_bounds__(256) void proj_kernel(
    const float* __restrict__ Q,
    const float* __restrict__ Wa,
    const float* __restrict__ Wb,
    const float* __restrict__ Wd)
{
    const float* W = (blockIdx.z == 0) ? Wa : (blockIdx.z == 1) ? Wb : Wd;
    float* Out     = (blockIdx.z == 0) ? g_A : (blockIdx.z == 1) ? g_Bm : g_H;

    __shared__ float Xs[16][68];
    __shared__ float Ws[16][68];

    int tid = threadIdx.x;
    int m0 = blockIdx.x * 64;
    int n0 = blockIdx.y * 64;
    int ty = tid >> 4;      // 0..15
    int tx = tid & 15;      // 0..15

    int lr = tid >> 2;          // 0..63 (row within tile)
    int lk = (tid & 3) * 4;     // 0,4,8,12 (k within tile)

    float acc[4][4];
#pragma unroll
    for (int m = 0; m < 4; m++)
#pragma unroll
        for (int n = 0; n < 4; n++) acc[m][n] = 0.f;

    for (int k0 = 0; k0 < Dx; k0 += 16) {
        float4 xv = *(const float4*)(Q + (m0 + lr) * Dx + k0 + lk);
        float4 wv = *(const float4*)(W + (n0 + lr) * Dx + k0 + lk);
        Xs[lk + 0][lr] = xv.x; Xs[lk + 1][lr] = xv.y;
        Xs[lk + 2][lr] = xv.z; Xs[lk + 3][lr] = xv.w;
        Ws[lk + 0][lr] = wv.x; Ws[lk + 1][lr] = wv.y;
        Ws[lk + 2][lr] = wv.z; Ws[lk + 3][lr] = wv.w;
        __syncthreads();
#pragma unroll
        for (int kk = 0; kk < 16; kk++) {
            float xr[4], wr[4];
#pragma unroll
            for (int m = 0; m < 4; m++) xr[m] = Xs[kk][ty * 4 + m];
#pragma unroll
            for (int n = 0; n < 4; n++) wr[n] = Ws[kk][tx * 4 + n];
#pragma unroll
            for (int m = 0; m < 4; m++)
#pragma unroll
                for (int n = 0; n < 4; n++)
                    acc[m][n] = fmaf(xr[m], wr[n], acc[m][n]);
        }
        __syncthreads();
    }

#pragma unroll
    for (int m = 0; m < 4; m++) {
        int row = m0 + ty * 4 + m;
#pragma unroll
        for (int n = 0; n < 4; n++)
            Out[row * Dx + n0 + tx * 4 + n] = acc[m][n];
    }
}

// ---------------------------------------------------------------------------
// Kernel 2: edge scores + mask + softmax -> g_W.
// Block handles (b, 8 rows i). 256 threads: warp il = tid/32 owns row i0+il,
// lane jl owns columns j = jl + 32*g, g=0..7. Bm staged transposed in shared
// per 32-wide c-chunk.
// ---------------------------------------------------------------------------
__global__ __launch_bounds__(256) void edge_kernel(
    const int* __restrict__ dep,
    const float* __restrict__ w2)
{
    int b  = blockIdx.y;
    int i0 = blockIdx.x * 8;

    __shared__ float Ash[8][256];
    __shared__ float Bt[32][257];
    __shared__ float w2s[256];

    int tid = threadIdx.x;

    // load 8 A rows (coalesced)
#pragma unroll
    for (int e = tid; e < 8 * 256; e += 256) {
        int il = e >> 8, c = e & 255;
        Ash[il][c] = g_A[(b * Lx + i0 + il) * Dx + c];
    }
    w2s[tid] = w2[tid];

    int il = tid >> 5;   // 0..7 : local row (constant per warp)
    int jl = tid & 31;   // lane : base column

    float acc[8];
#pragma unroll
    for (int g = 0; g < 8; g++) acc[g] = 0.f;

    const float* Bbase = g_Bm + b * Lx * Dx;

    for (int c0 = 0; c0 < Dx; c0 += 32) {
        __syncthreads();
        // load Bm[:,c0:c0+32] transposed into Bt[cl][j]
#pragma unroll
        for (int p = 0; p < 8; p++) {
            int e = p * 1024 + tid * 4;
            int j = e >> 5;
            int cl = e & 31;
            float4 v = *(const float4*)(Bbase + j * Dx + c0 + cl);
            Bt[cl + 0][j] = v.x; Bt[cl + 1][j] = v.y;
            Bt[cl + 2][j] = v.z; Bt[cl + 3][j] = v.w;
        }
        __syncthreads();
#pragma unroll 8
        for (int cl = 0; cl < 32; cl++) {
            float a = Ash[il][c0 + cl];   // warp-uniform broadcast
            float u = w2s[c0 + cl];       // warp-uniform broadcast
#pragma unroll
            for (int g = 0; g < 8; g++) {
                float s = a + Bt[cl][jl + 32 * g];   // lane-consecutive, no conflicts
                acc[g] = fmaf(fmaxf(s, 0.f), u, acc[g]);
            }
        }
    }

    // mask, softmax over j (whole row lives in this warp), then re-mask
    int i = i0 + il;
    const int* depRow = dep + (b * Lx + i) * Lx;

    float T[8];
    int   mk[8];
    float mx = -1e30f;
#pragma unroll
    for (int g = 0; g < 8; g++) {
        int m = depRow[jl + 32 * g];
        mk[g] = (m > 0);
        T[g] = mk[g] ? acc[g] : -100.0f;
        mx = fmaxf(mx, T[g]);
    }
#pragma unroll
    for (int off = 16; off > 0; off >>= 1)
        mx = fmaxf(mx, __shfl_xor_sync(0xffffffffu, mx, off));

    float E[8];
    float sum = 0.f;
#pragma unroll
    for (int g = 0; g < 8; g++) {
        E[g] = expf(T[g] - mx);
        sum += E[g];
    }
#pragma unroll
    for (int off = 16; off > 0; off >>= 1)
        sum += __shfl_xor_sync(0xffffffffu, sum, off);

    float inv = 1.0f / sum;
    float* wRow = g_W + (b * Lx + i) * Lx;
#pragma unroll
    for (int g = 0; g < 8; g++)
        wRow[jl + 32 * g] = mk[g] ? (E[g] * inv) : 0.f;
}

// ---------------------------------------------------------------------------
// Kernel 3: agg = w @ H per batch, out = relu(q + agg).  NN GEMM 256x256x256.
// BM=32 (i), BN=64 (c), BK=16, 256 threads, 2x4 per thread.
// grid (8, 4, B) = 256 blocks.
// ---------------------------------------------------------------------------
__global__ __launch_bounds__(256) void agg_kernel(
    const float* __restrict__ Q,
    float* __restrict__ out)
{
    int b  = blockIdx.z;
    int i0 = blockIdx.x * 32;
    int c0 = blockIdx.y * 64;

    __shared__ float Wsh[16][36];
    __shared__ float Hs[16][68];

    int tid = threadIdx.x;
    int ty = tid >> 4;   // 0..15 -> 2 rows each
    int tx = tid & 15;   // 0..15 -> 4 cols each

    const float* Wb_ = g_W + b * Lx * Lx;
    const float* Hb  = g_H + b * Lx * Dx;

    float acc[2][4];
#pragma unroll
    for (int m = 0; m < 2; m++)
#pragma unroll
        for (int n = 0; n < 4; n++) acc[m][n] = 0.f;

    for (int k0 = 0; k0 < Lx; k0 += 16) {
        {   // load W tile [32 rows][16 k], transposed
            int e = tid * 2;
            int r = e >> 4;
            int kk = e & 15;
            float2 wv = *(const float2*)(Wb_ + (i0 + r) * Lx + k0 + kk);
            Wsh[kk + 0][r] = wv.x;
            Wsh[kk + 1][r] = wv.y;
        }
        {   // load H tile [16 k][64 c]
            int e = tid * 4;
            int kk = e >> 6;
            int c = e & 63;
            float4 hv = *(const float4*)(Hb + (k0 + kk) * Dx + c0 + c);
            *(float4*)&Hs[kk][c] = hv;
        }
        __syncthreads();
#pragma unroll
        for (int kk = 0; kk < 16; kk++) {
            float w0 = Wsh[kk][ty * 2 + 0];
            float w1 = Wsh[kk][ty * 2 + 1];
            float4 h = *(const float4*)&Hs[kk][tx * 4];
            acc[0][0] = fmaf(w0, h.x, acc[0][0]);
            acc[0][1] = fmaf(w0, h.y, acc[0][1]);
            acc[0][2] = fmaf(w0, h.z, acc[0][2]);
            acc[0][3] = fmaf(w0, h.w, acc[0][3]);
            acc[1][0] = fmaf(w1, h.x, acc[1][0]);
            acc[1][1] = fmaf(w1, h.y, acc[1][1]);
            acc[1][2] = fmaf(w1, h.z, acc[1][2]);
            acc[1][3] = fmaf(w1, h.w, acc[1][3]);
        }
        __syncthreads();
    }

#pragma unroll
    for (int m = 0; m < 2; m++) {
        int i = i0 + ty * 2 + m;
        long base = (long)(b * Lx + i) * Dx + c0 + tx * 4;
#pragma unroll
        for (int n = 0; n < 4; n++) {
            float q = Q[base + n];
            out[base + n] = fmaxf(q + acc[m][n], 0.f);
        }
    }
}

// ---------------------------------------------------------------------------
// Tail: cast wordlens + syntactic_dep into the output buffer (tuple outputs).
// ---------------------------------------------------------------------------
__global__ void tail_kernel(const int* __restrict__ wl,
                            const int* __restrict__ dep,
                            float* __restrict__ dst)
{
    int t = blockIdx.x * blockDim.x + threadIdx.x;
    if (t < Bx) dst[t] = (float)wl[t];
    if (t < BLL) dst[Bx + t] = (float)dep[t];
}

// ---------------------------------------------------------------------------
extern "C" void kernel_launch(void* const* d_in, const int* in_sizes, int n_in,
                              void* d_out, int out_size)
{
    const float* Q   = (const float*)d_in[0];
    const int*   wl  = (const int*)d_in[1];
    const int*   dep = (const int*)d_in[2];
    const float* Wa  = (const float*)d_in[3];
    const float* Wb  = (const float*)d_in[4];
    const float* w2  = (const float*)d_in[5];
    const float* Wd  = (const float*)d_in[6];
    float* out = (float*)d_out;

    // projections: A, Bm, H
    proj_kernel<<<dim3(32, 4, 3), 256>>>(Q, Wa, Wb, Wd);
    // edge scores + softmax -> g_W
    edge_kernel<<<dim3(32, Bx), 256>>>(dep, w2);
    // aggregation + residual relu -> out[0 : B*L*D]
    agg_kernel<<<dim3(8, 4, Bx), 256>>>(Q, out);

    // tuple tail outputs if the harness expects them
    if (out_size >= BLD + Bx + BLL) {
        tail_kernel<<<(BLL + 255) / 256, 256>>>(wl, dep, out + BLD);
    }
}

// round 2
// speedup vs baseline: 1.0740x; 1.0740x over previous
#include <cuda_runtime.h>
#include <cuda_bf16.h>

// Problem constants
#define Bx 8
#define Lx 256
#define Dx 256
#define BLD (Bx*Lx*Dx)   // 524288
#define BLL (Bx*Lx*Lx)   // 524288

typedef unsigned long long u64;

// Scratch (device globals — no allocation allowed)
__device__ float g_A[BLD];   // Q @ Wa^T
__device__ float g_Bm[BLD];  // Q @ Wb^T
__device__ float g_H[BLD];   // Q @ Wd^T
__device__ float g_W[BLL];   // softmax weights

// ---- packed f32x2 helpers (Blackwell) --------------------------------------
__device__ __forceinline__ u64 pack2(float lo, float hi) {
    u64 r; asm("mov.b64 %0,{%1,%2};" : "=l"(r) : "f"(lo), "f"(hi)); return r;
}
__device__ __forceinline__ void unpack2(u64 v, float& lo, float& hi) {
    asm("mov.b64 {%0,%1},%2;" : "=f"(lo), "=f"(hi) : "l"(v));
}
__device__ __forceinline__ u64 ffma2(u64 a, u64 b, u64 c) {
    u64 d; asm("fma.rn.f32x2 %0,%1,%2,%3;" : "=l"(d) : "l"(a), "l"(b), "l"(c)); return d;
}
__device__ __forceinline__ u64 fadd2(u64 a, u64 b) {
    u64 d; asm("add.rn.f32x2 %0,%1,%2;" : "=l"(d) : "l"(a), "l"(b)); return d;
}

// ---------------------------------------------------------------------------
// Kernel 1: projections. C[m,n] = sum_k X[m,k] * W[n,k]  (NT GEMM)
// M = 2048, N = 256, K = 256. blockIdx.z picks {Wa,Wb,Wd}.
// BM=128, BN=64, BK=16, 128 threads, 8x8 per thread, f32x2 packed.
// ---------------------------------------------------------------------------
__global__ __launch_bounds__(128) void proj_kernel(
    const float* __restrict__ Q,
    const float* __restrict__ Wa,
    const float* __restrict__ Wb,
    const float* __restrict__ Wd)
{
    const float* W = (blockIdx.z == 0) ? Wa : (blockIdx.z == 1) ? Wb : Wd;
    float* Out     = (blockIdx.z == 0) ? g_A : (blockIdx.z == 1) ? g_Bm : g_H;

    __shared__ float Xs[16][132];
    __shared__ float Ws[16][68];

    int tid = threadIdx.x;
    int m0 = blockIdx.x * 128;
    int n0 = blockIdx.y * 64;
    int ty = tid >> 3;    // 0..15 -> 8 rows each
    int tx = tid & 7;     // 0..7  -> 8 cols each

    u64 acc[8][4];
#pragma unroll
    for (int m = 0; m < 8; m++)
#pragma unroll
        for (int n = 0; n < 4; n++) acc[m][n] = 0ull;

    for (int k0 = 0; k0 < Dx; k0 += 16) {
        // stage X tile 128x16 (transposed)
#pragma unroll
        for (int p = 0; p < 4; p++) {
            int e = tid * 4 + p * 512;
            int r = e >> 4, lk = e & 15;
            float4 v = *(const float4*)(Q + (m0 + r) * Dx + k0 + lk);
            Xs[lk + 0][r] = v.x; Xs[lk + 1][r] = v.y;
            Xs[lk + 2][r] = v.z; Xs[lk + 3][r] = v.w;
        }
        // stage W tile 64x16 (transposed)
#pragma unroll
        for (int p = 0; p < 2; p++) {
            int e = tid * 4 + p * 512;
            int r = e >> 4, lk = e & 15;
            float4 v = *(const float4*)(W + (n0 + r) * Dx + k0 + lk);
            Ws[lk + 0][r] = v.x; Ws[lk + 1][r] = v.y;
            Ws[lk + 2][r] = v.z; Ws[lk + 3][r] = v.w;
        }
        __syncthreads();
#pragma unroll
        for (int kk = 0; kk < 16; kk++) {
            float4 xa = *(const float4*)&Xs[kk][ty * 8];
            float4 xb = *(const float4*)&Xs[kk][ty * 8 + 4];
            float xs[8] = {xa.x, xa.y, xa.z, xa.w, xb.x, xb.y, xb.z, xb.w};
            u64 wv[4];
#pragma unroll
            for (int n = 0; n < 4; n++)
                wv[n] = *(const u64*)&Ws[kk][tx * 8 + 2 * n];
#pragma unroll
            for (int m = 0; m < 8; m++) {
                u64 xp = pack2(xs[m], xs[m]);
#pragma unroll
                for (int n = 0; n < 4; n++)
                    acc[m][n] = ffma2(xp, wv[n], acc[m][n]);
            }
        }
        __syncthreads();
    }

#pragma unroll
    for (int m = 0; m < 8; m++) {
        int row = m0 + ty * 8 + m;
        float o[8];
#pragma unroll
        for (int n = 0; n < 4; n++) unpack2(acc[m][n], o[2 * n], o[2 * n + 1]);
        float* dst = Out + row * Dx + n0 + tx * 8;
        *(float4*)(dst)     = make_float4(o[0], o[1], o[2], o[3]);
        *(float4*)(dst + 4) = make_float4(o[4], o[5], o[6], o[7]);
    }
}

// ---------------------------------------------------------------------------
// Kernel 2: edge scores + mask + softmax -> g_W, plus tail conversion.
// Block = (b, 16 rows i). 256 threads = 8 warps, 2 rows per warp.
// Lane jl owns j = gp*64 + jl*2 (+0/1), gp=0..3 -> 8 j per lane per row.
// ---------------------------------------------------------------------------
__device__ __forceinline__ void softmax_row(
    u64 acc[4], int b, int i, int jl,
    const int* __restrict__ dep, float* __restrict__ depout)
{
    const int* dr = dep + (b * Lx + i) * Lx;
    float T[8]; int mk[8];
    float mx = -1e30f;
#pragma unroll
    for (int gp = 0; gp < 4; gp++) {
        int j0 = gp * 64 + jl * 2;
        int2 m2 = *(const int2*)(dr + j0);
        float lo, hi; unpack2(acc[gp], lo, hi);
        mk[2 * gp]     = (m2.x > 0);
        mk[2 * gp + 1] = (m2.y > 0);
        T[2 * gp]     = mk[2 * gp]     ? lo : -100.0f;
        T[2 * gp + 1] = mk[2 * gp + 1] ? hi : -100.0f;
        mx = fmaxf(mx, fmaxf(T[2 * gp], T[2 * gp + 1]));
        if (depout) {
            float2 dv = make_float2((float)m2.x, (float)m2.y);
            *(float2*)(depout + (b * Lx + i) * Lx + j0) = dv;
        }
    }
#pragma unroll
    for (int off = 16; off > 0; off >>= 1)
        mx = fmaxf(mx, __shfl_xor_sync(0xffffffffu, mx, off));

    float E[8], sum = 0.f;
#pragma unroll
    for (int g = 0; g < 8; g++) { E[g] = expf(T[g] - mx); sum += E[g]; }
#pragma unroll
    for (int off = 16; off > 0; off >>= 1)
        sum += __shfl_xor_sync(0xffffffffu, sum, off);

    float inv = 1.0f / sum;
    float* wRow = g_W + (b * Lx + i) * Lx;
#pragma unroll
    for (int gp = 0; gp < 4; gp++) {
        float2 o;
        o.x = mk[2 * gp]     ? E[2 * gp]     * inv : 0.f;
        o.y = mk[2 * gp + 1] ? E[2 * gp + 1] * inv : 0.f;
        *(float2*)(wRow + gp * 64 + jl * 2) = o;
    }
}

__global__ __launch_bounds__(256) void edge_kernel(
    const int* __restrict__ dep,
    const float* __restrict__ w2,
    const int* __restrict__ wl,
    float* __restrict__ dst)   // out + BLD, or nullptr
{
    int b  = blockIdx.y;
    int i0 = blockIdx.x * 16;

    __shared__ float Ash[16][256];
    __shared__ float Bt[16][258];
    __shared__ float w2s[256];

    int tid = threadIdx.x;
    int w  = tid >> 5;   // warp 0..7 -> rows i0 + 2w, i0 + 2w + 1
    int jl = tid & 31;

    // stage 16 A rows
#pragma unroll
    for (int p = 0; p < 4; p++) {
        int e = tid * 4 + p * 1024;
        int il = e >> 8, c = e & 255;
        float4 v = *(const float4*)(g_A + (b * Lx + i0 + il) * Dx + c);
        *(float4*)&Ash[il][c] = v;
    }
    w2s[tid] = w2[tid];

    if (dst && blockIdx.x == 0 && blockIdx.y == 0 && tid < Bx)
        dst[tid] = (float)wl[tid];

    float* depout = dst ? dst + Bx : nullptr;

    u64 acc0[4], acc1[4];
#pragma unroll
    for (int gp = 0; gp < 4; gp++) { acc0[gp] = 0ull; acc1[gp] = 0ull; }

    const float* Bbase = g_Bm + b * Lx * Dx;
    int r0l = w * 2, r1l = w * 2 + 1;

    for (int c0 = 0; c0 < Dx; c0 += 16) {
        __syncthreads();
        // stage Bm[:, c0:c0+16] transposed: Bt[cl][j]
#pragma unroll
        for (int p = 0; p < 4; p++) {
            int e = tid * 4 + p * 1024;
            int j = e >> 4, cl = e & 15;
            float4 v = *(const float4*)(Bbase + j * Dx + c0 + cl);
            Bt[cl + 0][j] = v.x; Bt[cl + 1][j] = v.y;
            Bt[cl + 2][j] = v.z; Bt[cl + 3][j] = v.w;
        }
        __syncthreads();
#pragma unroll
        for (int cl = 0; cl < 16; cl++) {
            float a0 = Ash[r0l][c0 + cl];   // warp-uniform broadcast
            float a1 = Ash[r1l][c0 + cl];
            float u  = w2s[c0 + cl];
            u64 a0p = pack2(a0, a0);
            u64 a1p = pack2(a1, a1);
            u64 up  = pack2(u, u);
#pragma unroll
            for (int gp = 0; gp < 4; gp++) {
                u64 bt = *(const u64*)&Bt[cl][gp * 64 + jl * 2];  // LDS.64, conflict-free
                u64 s0 = fadd2(a0p, bt);
                u64 s1 = fadd2(a1p, bt);
                float x, y;
                unpack2(s0, x, y);
                u64 rr0 = pack2(fmaxf(x, 0.f), fmaxf(y, 0.f));
                unpack2(s1, x, y);
                u64 rr1 = pack2(fmaxf(x, 0.f), fmaxf(y, 0.f));
                acc0[gp] = ffma2(rr0, up, acc0[gp]);
                acc1[gp] = ffma2(rr1, up, acc1[gp]);
            }
        }
    }

    softmax_row(acc0, b, i0 + 2 * w,     jl, dep, depout);
    softmax_row(acc1, b, i0 + 2 * w + 1, jl, dep, depout);
}

// ---------------------------------------------------------------------------
// Kernel 3: agg = w @ H per batch, out = relu(q + agg).  NN GEMM 256x256x256.
// BM=64, BN=64, BK=16, 128 threads, 4x8 per thread, f32x2 packed.
// ---------------------------------------------------------------------------
__global__ __launch_bounds__(128) void agg_kernel(
    const float* __restrict__ Q,
    float* __restrict__ out)
{
    int b  = blockIdx.z;
    int i0 = blockIdx.x * 64;
    int c0 = blockIdx.y * 64;

    __shared__ float Wt[16][68];
    __shared__ float Hs[16][68];

    int tid = threadIdx.x;
    int ty = tid >> 3;  // 0..15 -> 4 rows each
    int tx = tid & 7;   // 0..7  -> 8 cols each

    const float* Wb_ = g_W + b * Lx * Lx;
    const float* Hb  = g_H + b * Lx * Dx;

    u64 acc[4][4];
#pragma unroll
    for (int m = 0; m < 4; m++)
#pragma unroll
        for (int n = 0; n < 4; n++) acc[m][n] = 0ull;

    for (int k0 = 0; k0 < Lx; k0 += 16) {
        // stage W tile 64(i) x 16(k), transposed
#pragma unroll
        for (int p = 0; p < 2; p++) {
            int e = tid * 4 + p * 512;
            int r = e >> 4, kk = e & 15;
            float4 v = *(const float4*)(Wb_ + (i0 + r) * Lx + k0 + kk);
            Wt[kk + 0][r] = v.x; Wt[kk + 1][r] = v.y;
            Wt[kk + 2][r] = v.z; Wt[kk + 3][r] = v.w;
        }
        // stage H tile 16(k) x 64(c)
#pragma unroll
        for (int p = 0; p < 2; p++) {
            int e = tid * 4 + p * 512;
            int kk = e >> 6, c = e & 63;
            *(float4*)&Hs[kk][c] = *(const float4*)(Hb + (k0 + kk) * Dx + c0 + c);
        }
        __syncthreads();
#pragma unroll
        for (int kk = 0; kk < 16; kk++) {
            float4 wv = *(const float4*)&Wt[kk][ty * 4];
            float ws[4] = {wv.x, wv.y, wv.z, wv.w};
            u64 h[4];
#pragma unroll
            for (int n = 0; n < 4; n++)
                h[n] = *(const u64*)&Hs[kk][tx * 8 + 2 * n];
#pragma unroll
            for (int m = 0; m < 4; m++) {
                u64 wp = pack2(ws[m], ws[m]);
#pragma unroll
                for (int n = 0; n < 4; n++)
                    acc[m][n] = ffma2(wp, h[n], acc[m][n]);
            }
        }
        __syncthreads();
    }

#pragma unroll
    for (int m = 0; m < 4; m++) {
        int i = i0 + ty * 4 + m;
        long base = (long)(b * Lx + i) * Dx + c0 + tx * 8;
        float4 q1 = *(const float4*)(Q + base);
        float4 q2 = *(const float4*)(Q + base + 4);
        float o[8];
#pragma unroll
        for (int n = 0; n < 4; n++) unpack2(acc[m][n], o[2 * n], o[2 * n + 1]);
        float4 r1 = make_float4(fmaxf(q1.x + o[0], 0.f), fmaxf(q1.y + o[1], 0.f),
                                fmaxf(q1.z + o[2], 0.f), fmaxf(q1.w + o[3], 0.f));
        float4 r2 = make_float4(fmaxf(q2.x + o[4], 0.f), fmaxf(q2.y + o[5], 0.f),
                                fmaxf(q2.z + o[6], 0.f), fmaxf(q2.w + o[7], 0.f));
        *(float4*)(out + base)     = r1;
        *(float4*)(out + base + 4) = r2;
    }
}

// ---------------------------------------------------------------------------
extern "C" void kernel_launch(void* const* d_in, const int* in_sizes, int n_in,
                              void* d_out, int out_size)
{
    const float* Q   = (const float*)d_in[0];
    const int*   wl  = (const int*)d_in[1];
    const int*   dep = (const int*)d_in[2];
    const float* Wa  = (const float*)d_in[3];
    const float* Wb  = (const float*)d_in[4];
    const float* w2  = (const float*)d_in[5];
    const float* Wd  = (const float*)d_in[6];
    float* out = (float*)d_out;

    float* dst = (out_size >= BLD + Bx + BLL) ? out + BLD : nullptr;

    // projections: A, Bm, H
    proj_kernel<<<dim3(16, 4, 3), 128>>>(Q, Wa, Wb, Wd);
    // edge scores + softmax -> g_W (+ tail conversions folded in)
    edge_kernel<<<dim3(16, Bx), 256>>>(dep, w2, wl, dst);
    // aggregation + residual relu -> out[0 : B*L*D]
    agg_kernel<<<dim3(4, 4, Bx), 128>>>(Q, out);
}